// round 11
// baseline (speedup 1.0000x reference)
#include <cuda_runtime.h>
#include <cuda_bf16.h>
#include <cstdint>

// Weighted AUC, single fused kernel. Data staged via cp.async.bulk (TMA bulk
// copy, one instruction per 8KB tile) -> SMEM, removing all per-lane L1TEX
// load processing; warps only do LDS + smem ATOMS. Labels are 0/1: one ATOMS
// per element into [tp NB | fp NB], bin+half folded into 2 FMA + F2I.
// area = sum_b fp[b]*(TP_above(b)+0.5*tp[b]); auc = area/(TP_tot*FP_tot).
// Last block per task finalizes and re-zeros global state (graph-replay safe).

#define T_TASKS 16
#define NB 4096
#define NPT 2097152
#define N4 (NPT / 4)             // 524288 float4 per task
#define CHUNKS 37                // 592 blocks = exactly 2 waves at 2 blocks/SM
#define PER_CHUNK 14171          // ceil(N4/37)
#define THREADS 512
#define BINS_PT (NB / THREADS)
#define STAGES 3
#define STAGE_F4 THREADS         // 512 float4 = 8KB per array per stage

// smem: hist 32KB | stages 3*3*8KB=72KB | 3 mbarriers
#define HIST_F    (2 * NB)
#define STAGE_OFF HIST_F                       // in floats
#define MBAR_OFF  (HIST_F + STAGES * 3 * STAGE_F4 * 4)   // in floats
#define SMEM_BYTES ((MBAR_OFF + 16) * 4)

__device__ float        g_hist[T_TASKS * 2 * NB];   // zero-init at load
__device__ unsigned int g_count[T_TASKS];           // zero-init at load

__device__ __forceinline__ void mbar_init(void* mbar, unsigned cnt) {
    unsigned m = (unsigned)__cvta_generic_to_shared(mbar);
    asm volatile("mbarrier.init.shared.b64 [%0], %1;" :: "r"(m), "r"(cnt) : "memory");
}
__device__ __forceinline__ void mbar_expect_tx(void* mbar, unsigned bytes) {
    unsigned m = (unsigned)__cvta_generic_to_shared(mbar);
    asm volatile("mbarrier.arrive.expect_tx.shared.b64 _, [%0], %1;"
                 :: "r"(m), "r"(bytes) : "memory");
}
__device__ __forceinline__ void mbar_wait(void* mbar, unsigned parity) {
    unsigned m = (unsigned)__cvta_generic_to_shared(mbar);
    asm volatile(
        "{\n\t.reg .pred P;\n"
        "WAIT_%=:\n\t"
        "mbarrier.try_wait.parity.acquire.cta.shared::cta.b64 P, [%0], %1, 0x989680;\n\t"
        "@P bra DONE_%=;\n\t"
        "bra WAIT_%=;\n"
        "DONE_%=:\n\t}"
        :: "r"(m), "r"(parity) : "memory");
}
__device__ __forceinline__ void bulk_cp(void* smem_dst, const void* gsrc,
                                        unsigned bytes, void* mbar) {
    unsigned d = (unsigned)__cvta_generic_to_shared(smem_dst);
    unsigned m = (unsigned)__cvta_generic_to_shared(mbar);
    asm volatile(
        "cp.async.bulk.shared::cta.global.mbarrier::complete_tx::bytes [%0], [%1], %2, [%3];"
        :: "r"(d), "l"(gsrc), "r"(bytes), "r"(m) : "memory");
}

__global__ void __launch_bounds__(THREADS, 2) auc_kernel(
    const float4* __restrict__ pp, const float4* __restrict__ ll,
    const float4* __restrict__ ww, float* __restrict__ out)
{
    extern __shared__ __align__(16) float sh[];
    float4*   stage = (float4*)(sh + STAGE_OFF);   // [STAGES][3][STAGE_F4]
    uint64_t* mbar  = (uint64_t*)(sh + MBAR_OFF);  // [STAGES]

    const int task = blockIdx.y;
    const int t    = threadIdx.x;

    for (int i = t; i < 2 * NB; i += THREADS) sh[i] = 0.0f;
    if (t < STAGES) mbar_init(&mbar[t], 1u);
    asm volatile("fence.proxy.async.shared::cta;" ::: "memory");
    __syncthreads();

    // ---- histogram phase: 3-stage TMA-bulk ring ----
    {
        const int start = blockIdx.x * PER_CHUNK;
        const int end   = (start + PER_CHUNK < N4) ? start + PER_CHUNK : N4;
        const int base  = task * N4 + start;
        const int cnt   = end - start;                 // float4 count
        const int KTOT  = (cnt + THREADS - 1) / THREADS;

#define SLOT(s, a) (stage + ((s) * 3 + (a)) * STAGE_F4)

        if (t == 0) {
#pragma unroll
            for (int s = 0; s < STAGES; ++s) {
                if (s < KTOT) {
                    int n = cnt - s * THREADS; n = n > THREADS ? THREADS : n;
                    unsigned bytes = (unsigned)n * 16u;
                    mbar_expect_tx(&mbar[s], 3u * bytes);
                    bulk_cp(SLOT(s, 0), pp + base + s * THREADS, bytes, &mbar[s]);
                    bulk_cp(SLOT(s, 1), ll + base + s * THREADS, bytes, &mbar[s]);
                    bulk_cp(SLOT(s, 2), ww + base + s * THREADS, bytes, &mbar[s]);
                }
            }
        }

        for (int k = 0; k < KTOT; ++k) {
            const int slot = k % STAGES;
            mbar_wait(&mbar[slot], (unsigned)((k / STAGES) & 1));

            const int i = k * THREADS + t;
            if (i < cnt) {
                float4 pv = SLOT(slot, 0)[t];
                float4 lv = SLOT(slot, 1)[t];
                float4 wv = SLOT(slot, 2)[t];
#define DO_COMP(c)                                                        \
                {                                                         \
                    float offf = fmaf(lv.c, -(float)NB,                   \
                                      fmaf(pv.c, (float)NB, (float)NB));  \
                    atomicAdd(sh + (int)offf, wv.c);                      \
                }
                DO_COMP(x) DO_COMP(y) DO_COMP(z) DO_COMP(w)
#undef DO_COMP
            }
            __syncthreads();                           // slot fully consumed

            const int kn = k + STAGES;
            if (kn < KTOT && t == 0) {
                int n = cnt - kn * THREADS; n = n > THREADS ? THREADS : n;
                unsigned bytes = (unsigned)n * 16u;
                mbar_expect_tx(&mbar[slot], 3u * bytes);
                bulk_cp(SLOT(slot, 0), pp + base + kn * THREADS, bytes, &mbar[slot]);
                bulk_cp(SLOT(slot, 1), ll + base + kn * THREADS, bytes, &mbar[slot]);
                bulk_cp(SLOT(slot, 2), ww + base + kn * THREADS, bytes, &mbar[slot]);
            }
        }
#undef SLOT
    }
    __syncthreads();

    // ---- flush to global ----
    float* gh = g_hist + task * 2 * NB;
    for (int i = t; i < 2 * NB; i += THREADS)
        atomicAdd(gh + i, sh[i]);
    __threadfence();
    __syncthreads();

    // ---- elect last block per task ----
    __shared__ unsigned s_last;
    if (t == 0) s_last = atomicAdd(&g_count[task], 1u);
    __syncthreads();
    if (s_last != CHUNKS - 1) return;
    __threadfence();   // acquire: see all other blocks' hist atomics

    // ---- finalize (this block only): suffix scan + area + auc ----
    float* fsum = sh;
    float  th[BINS_PT], loc[BINS_PT];
    float  s = 0.0f;
#pragma unroll
    for (int j = BINS_PT - 1; j >= 0; --j) {
        th[j] = gh[t * BINS_PT + j];
        s += th[j];
        loc[j] = s;
    }
    __syncthreads();
    fsum[t] = s;
    __syncthreads();

    for (int off = 1; off < THREADS; off <<= 1) {
        float v = (t + off < THREADS) ? fsum[t + off] : 0.0f;
        __syncthreads();
        fsum[t] += v;
        __syncthreads();
    }
    const float above    = (t + 1 < THREADS) ? fsum[t + 1] : 0.0f;
    const float tp_total = fsum[0];
    __syncthreads();

    double a = 0.0, f = 0.0;
#pragma unroll
    for (int j = 0; j < BINS_PT; ++j) {
        float fv  = gh[NB + t * BINS_PT + j];
        float lut = above + loc[j] - 0.5f * th[j];
        a += (double)fv * (double)lut;
        f += (double)fv;
    }

#pragma unroll
    for (int off = 16; off; off >>= 1) {
        a += __shfl_down_sync(0xffffffffu, a, off);
        f += __shfl_down_sync(0xffffffffu, f, off);
    }
    double* sred = (double*)sh;
    const int warp = t >> 5, lane = t & 31;
    __syncthreads();
    if (lane == 0) { sred[warp] = a; sred[16 + warp] = f; }
    __syncthreads();

    if (t == 0) {
        double ta = 0.0, tf = 0.0;
#pragma unroll
        for (int k = 0; k < THREADS / 32; ++k) { ta += sred[k]; tf += sred[16 + k]; }
        double denom = tf * (double)tp_total;
        out[task] = (denom == 0.0) ? 0.5f : (float)(ta / denom);
        g_count[task] = 0u;
    }

    for (int i = t; i < 2 * NB; i += THREADS) gh[i] = 0.0f;
}

extern "C" void kernel_launch(void* const* d_in, const int* in_sizes, int n_in,
                              void* d_out, int out_size) {
    int off = (n_in >= 4 && in_sizes[0] == 1) ? 1 : 0;
    const float4* p = (const float4*)d_in[off + 0];
    const float4* l = (const float4*)d_in[off + 1];
    const float4* w = (const float4*)d_in[off + 2];

    static int attr_set = 0;   // idempotent attribute set (not a work guard)
    if (!attr_set) {
        cudaFuncSetAttribute(auc_kernel,
                             cudaFuncAttributeMaxDynamicSharedMemorySize,
                             SMEM_BYTES);
        attr_set = 1;
    }

    dim3 g(CHUNKS, T_TASKS);
    auc_kernel<<<g, THREADS, SMEM_BYTES>>>(p, l, w, (float*)d_out);
}

// round 14
// speedup vs baseline: 1.3186x; 1.3186x over previous
#include <cuda_runtime.h>
#include <cuda_bf16.h>
#include <cstdint>

// Weighted AUC, single fused kernel, WARP-SPECIALIZED:
//   threads 0-255   : producers — cp.async.cg 16B into a 3-stage smem ring
//   threads 256-511 : consumers — LDS + one smem ATOMS per element
// One __syncthreads per 24KB stage; ring: iter k fills buf (k+2)%3, drains k%3.
// Labels are 0/1: off = (int)fma(l,-NB, fma(p,NB,NB)) selects [tp NB | fp NB].
// area = sum_b fp[b]*(TP_above(b)+0.5*tp[b]); auc = area/(TP_tot*FP_tot).
// Last block per task finalizes and re-zeros global state (graph-replay safe).

#define T_TASKS 16
#define NB 4096
#define NPT 2097152
#define N4 (NPT / 4)             // 524288 float4 per task
#define CHUNKS 37                // 592 blocks = exactly 2 waves at 2 blocks/SM
#define PER_CHUNK 14171          // ceil(N4/37)
#define THREADS 512
#define PROD 256
#define BINS_PT (NB / THREADS)
#define STAGES 3
#define STAGE_F4 512             // 512 float4 = 8KB per array per stage

#define HIST_F (2 * NB)                                   // 8192 floats = 32KB
#define SMEM_BYTES (HIST_F * 4 + STAGES * 3 * STAGE_F4 * 16)   // 32KB + 72KB

__device__ float        g_hist[T_TASKS * 2 * NB];   // zero-init at load
__device__ unsigned int g_count[T_TASKS];           // zero-init at load

__device__ __forceinline__ void cp16(void* smem_dst, const void* gsrc) {
    unsigned a = (unsigned)__cvta_generic_to_shared(smem_dst);
    asm volatile("cp.async.cg.shared.global [%0], [%1], 16;\n" :: "r"(a), "l"(gsrc));
}
#define CP_COMMIT() asm volatile("cp.async.commit_group;\n" ::: "memory")
#define CP_WAIT1()  asm volatile("cp.async.wait_group 1;\n" ::: "memory")

__global__ void __launch_bounds__(THREADS, 2) auc_kernel(
    const float4* __restrict__ pp, const float4* __restrict__ ll,
    const float4* __restrict__ ww, float* __restrict__ out)
{
    extern __shared__ __align__(16) float sh[];          // hist [2*NB]
    float4* stage = (float4*)(sh + HIST_F);              // [STAGES][3][STAGE_F4]
#define SLOT(s, a) (stage + ((s) * 3 + (a)) * STAGE_F4)

    const int task = blockIdx.y;
    const int t    = threadIdx.x;

    for (int i = t; i < 2 * NB; i += THREADS) sh[i] = 0.0f;
    __syncthreads();

    // ---- histogram phase: specialized producer/consumer 3-stage ring ----
    {
        const int start = blockIdx.x * PER_CHUNK;
        const int end   = (start + PER_CHUNK < N4) ? start + PER_CHUNK : N4;
        const int base  = task * N4 + start;
        const int cnt   = end - start;                   // float4 count
        const int KTOT  = (cnt + STAGE_F4 - 1) / STAGE_F4;

        if (t < PROD) {
            // ---------------- producer ----------------
            const int p = t;
#define ISSUE(k)                                                          \
            {                                                             \
                const int b = (k) % STAGES;                               \
                const int f0 = (k) * STAGE_F4 + p;                        \
                _Pragma("unroll")                                         \
                for (int r = 0; r < 2; ++r) {                             \
                    const int j = f0 + r * PROD;                          \
                    if (j < cnt) {                                        \
                        cp16(SLOT(b, 0) + p + r * PROD, pp + base + j);   \
                        cp16(SLOT(b, 1) + p + r * PROD, ll + base + j);   \
                        cp16(SLOT(b, 2) + p + r * PROD, ww + base + j);   \
                    }                                                     \
                }                                                         \
            }
            ISSUE(0); CP_COMMIT();
            if (1 < KTOT) ISSUE(1);
            CP_COMMIT();
            CP_WAIT1();                                  // stage 0 complete
            for (int k = 0; k < KTOT; ++k) {
                __syncthreads();                         // stage k published
                if (k + 2 < KTOT) ISSUE(k + 2);          // fills (k+2)%3
                CP_COMMIT();
                CP_WAIT1();                              // stage k+1 complete
            }
#undef ISSUE
        } else {
            // ---------------- consumer ----------------
            const int c = t - PROD;
            for (int k = 0; k < KTOT; ++k) {
                __syncthreads();                         // stage k ready
                const int b  = k % STAGES;
                const int f0 = k * STAGE_F4 + c;
#pragma unroll
                for (int r = 0; r < 2; ++r) {
                    const int j = f0 + r * PROD;
                    if (j < cnt) {
                        float4 pv = SLOT(b, 0)[c + r * PROD];
                        float4 lv = SLOT(b, 1)[c + r * PROD];
                        float4 wv = SLOT(b, 2)[c + r * PROD];
#define DO_COMP(cc)                                                       \
                        {                                                 \
                            float offf = fmaf(lv.cc, -(float)NB,          \
                                     fmaf(pv.cc, (float)NB, (float)NB));  \
                            atomicAdd(sh + (int)offf, wv.cc);             \
                        }
                        DO_COMP(x) DO_COMP(y) DO_COMP(z) DO_COMP(w)
#undef DO_COMP
                    }
                }
            }
        }
    }
    __syncthreads();

    // ---- flush to global ----
    float* gh = g_hist + task * 2 * NB;
    for (int i = t; i < 2 * NB; i += THREADS)
        atomicAdd(gh + i, sh[i]);
    __threadfence();
    __syncthreads();

    // ---- elect last block per task ----
    __shared__ unsigned s_last;
    if (t == 0) s_last = atomicAdd(&g_count[task], 1u);
    __syncthreads();
    if (s_last != CHUNKS - 1) return;
    __threadfence();   // acquire: see all other blocks' hist atomics

    // ---- finalize (this block only): suffix scan + area + auc ----
    float* fsum = sh;
    float  th[BINS_PT], loc[BINS_PT];
    float  s = 0.0f;
#pragma unroll
    for (int j = BINS_PT - 1; j >= 0; --j) {
        th[j] = gh[t * BINS_PT + j];
        s += th[j];
        loc[j] = s;
    }
    __syncthreads();
    fsum[t] = s;
    __syncthreads();

    for (int off = 1; off < THREADS; off <<= 1) {
        float v = (t + off < THREADS) ? fsum[t + off] : 0.0f;
        __syncthreads();
        fsum[t] += v;
        __syncthreads();
    }
    const float above    = (t + 1 < THREADS) ? fsum[t + 1] : 0.0f;
    const float tp_total = fsum[0];
    __syncthreads();

    double a = 0.0, f = 0.0;
#pragma unroll
    for (int j = 0; j < BINS_PT; ++j) {
        float fv  = gh[NB + t * BINS_PT + j];
        float lut = above + loc[j] - 0.5f * th[j];
        a += (double)fv * (double)lut;
        f += (double)fv;
    }

#pragma unroll
    for (int off = 16; off; off >>= 1) {
        a += __shfl_down_sync(0xffffffffu, a, off);
        f += __shfl_down_sync(0xffffffffu, f, off);
    }
    double* sred = (double*)sh;
    const int warp = t >> 5, lane = t & 31;
    __syncthreads();
    if (lane == 0) { sred[warp] = a; sred[16 + warp] = f; }
    __syncthreads();

    if (t == 0) {
        double ta = 0.0, tf = 0.0;
#pragma unroll
        for (int k = 0; k < THREADS / 32; ++k) { ta += sred[k]; tf += sred[16 + k]; }
        double denom = tf * (double)tp_total;
        out[task] = (denom == 0.0) ? 0.5f : (float)(ta / denom);
        g_count[task] = 0u;
    }

    for (int i = t; i < 2 * NB; i += THREADS) gh[i] = 0.0f;
#undef SLOT
}

extern "C" void kernel_launch(void* const* d_in, const int* in_sizes, int n_in,
                              void* d_out, int out_size) {
    int off = (n_in >= 4 && in_sizes[0] == 1) ? 1 : 0;
    const float4* p = (const float4*)d_in[off + 0];
    const float4* l = (const float4*)d_in[off + 1];
    const float4* w = (const float4*)d_in[off + 2];

    static int attr_set = 0;   // idempotent attribute set (not a work guard)
    if (!attr_set) {
        cudaFuncSetAttribute(auc_kernel,
                             cudaFuncAttributeMaxDynamicSharedMemorySize,
                             SMEM_BYTES);
        attr_set = 1;
    }

    dim3 g(CHUNKS, T_TASKS);
    auc_kernel<<<g, THREADS, SMEM_BYTES>>>(p, l, w, (float*)d_out);
}

// round 15
// speedup vs baseline: 1.9721x; 1.4956x over previous
#include <cuda_runtime.h>
#include <cuda_bf16.h>

// Weighted AUC, single fused kernel — converged R5/R9 structure, NB=2048.
// Labels are exactly 0/1: one smem ATOMS per element into [tp NB | fp NB],
// bin+half select folded into 2 FMA + F2I:
//   off = (int)fma(l, -NB, fma(p, NB, NB))   (exact: p in [0,1), l in {0,1})
// area = sum_b fp[b]*(TP_above(b)+0.5*tp[b]); auc = area/(TP_tot*FP_tot).
// Last block per task finalizes in-kernel and restores zeroed global state so
// every graph replay sees identical initial state.

#define T_TASKS 16
#define NB 2048                // prediction bins, uniform [0,1)
#define NPT 2097152
#define N4 (NPT / 4)           // 524288 float4 per task
#define CHUNKS 37              // 16*37 = 592 blocks = 4 per SM on 148 SMs
#define PER_CHUNK 14171        // ceil(N4/37)
#define THREADS 512
#define BINS_PT (NB / THREADS) // 4 bins per thread in finalize

__device__ float        g_hist[T_TASKS * 2 * NB];   // [tp NB][fp NB] per task, zero-init
__device__ unsigned int g_count[T_TASKS];           // zero-init

__global__ void __launch_bounds__(THREADS, 4) auc_kernel(
    const float4* __restrict__ pp, const float4* __restrict__ ll,
    const float4* __restrict__ ww, float* __restrict__ out)
{
    __shared__ __align__(16) float sh[2 * NB];   // 16 KB: [tp NB][fp NB]
    const int task = blockIdx.y;
    const int t    = threadIdx.x;

    for (int i = t; i < 2 * NB; i += THREADS) sh[i] = 0.0f;
    __syncthreads();

    // ---- histogram phase (proven R5 loop shape + R9 FMA diet) ----
    {
        const int start = blockIdx.x * PER_CHUNK;
        const int end   = (start + PER_CHUNK < N4) ? start + PER_CHUNK : N4;
        const int base  = task * N4 + start;
        const int cnt   = end - start;

#pragma unroll 2
        for (int i = t; i < cnt; i += THREADS) {
            float4 pv = __ldcs(pp + base + i);
            float4 lv = __ldcs(ll + base + i);
            float4 wv = __ldcs(ww + base + i);
#define DO_COMP(c)                                                        \
            {                                                             \
                float offf = fmaf(lv.c, -(float)NB,                       \
                                  fmaf(pv.c, (float)NB, (float)NB));      \
                atomicAdd(sh + (int)offf, wv.c);                          \
            }
            DO_COMP(x) DO_COMP(y) DO_COMP(z) DO_COMP(w)
#undef DO_COMP
        }
    }
    __syncthreads();

    // ---- flush to global ----
    float* gh = g_hist + task * 2 * NB;
    for (int i = t; i < 2 * NB; i += THREADS)
        atomicAdd(gh + i, sh[i]);
    __threadfence();
    __syncthreads();

    // ---- elect last block per task ----
    __shared__ unsigned s_last;
    if (t == 0) s_last = atomicAdd(&g_count[task], 1u);
    __syncthreads();
    if (s_last != CHUNKS - 1) return;
    __threadfence();   // acquire: see all other blocks' hist atomics

    // ---- finalize (this block only): suffix scan + area + auc ----
    float* fsum = sh;                 // reuse smem (512 floats)
    float  th[BINS_PT], loc[BINS_PT];
    float  s = 0.0f;
#pragma unroll
    for (int j = BINS_PT - 1; j >= 0; --j) {
        th[j] = gh[t * BINS_PT + j];
        s += th[j];
        loc[j] = s;                   // inclusive suffix within thread's bins
    }
    __syncthreads();
    fsum[t] = s;
    __syncthreads();

    // Hillis-Steele inclusive suffix scan over 512 thread totals
    for (int off = 1; off < THREADS; off <<= 1) {
        float v = (t + off < THREADS) ? fsum[t + off] : 0.0f;
        __syncthreads();
        fsum[t] += v;
        __syncthreads();
    }
    const float above    = (t + 1 < THREADS) ? fsum[t + 1] : 0.0f;
    const float tp_total = fsum[0];
    __syncthreads();

    double a = 0.0, f = 0.0;
#pragma unroll
    for (int j = 0; j < BINS_PT; ++j) {
        float fv  = gh[NB + t * BINS_PT + j];
        float lut = above + loc[j] - 0.5f * th[j];
        a += (double)fv * (double)lut;
        f += (double)fv;
    }

#pragma unroll
    for (int off = 16; off; off >>= 1) {
        a += __shfl_down_sync(0xffffffffu, a, off);
        f += __shfl_down_sync(0xffffffffu, f, off);
    }
    double* sred = (double*)sh;       // reuse smem (32 doubles)
    const int warp = t >> 5, lane = t & 31;
    __syncthreads();
    if (lane == 0) { sred[warp] = a; sred[16 + warp] = f; }
    __syncthreads();

    if (t == 0) {
        double ta = 0.0, tf = 0.0;
#pragma unroll
        for (int k = 0; k < THREADS / 32; ++k) { ta += sred[k]; tf += sred[16 + k]; }
        double denom = tf * (double)tp_total;
        out[task] = (denom == 0.0) ? 0.5f : (float)(ta / denom);
        g_count[task] = 0u;           // restore invariant
    }

    // restore g_hist zeros for next call / replay
    for (int i = t; i < 2 * NB; i += THREADS) gh[i] = 0.0f;
}

extern "C" void kernel_launch(void* const* d_in, const int* in_sizes, int n_in,
                              void* d_out, int out_size) {
    int off = (n_in >= 4 && in_sizes[0] == 1) ? 1 : 0;
    const float4* p = (const float4*)d_in[off + 0];
    const float4* l = (const float4*)d_in[off + 1];
    const float4* w = (const float4*)d_in[off + 2];

    dim3 g(CHUNKS, T_TASKS);
    auc_kernel<<<g, THREADS>>>(p, l, w, (float*)d_out);
}